// round 11
// baseline (speedup 1.0000x reference)
#include <cuda_runtime.h>
#include <cuda.h>
#include <math.h>
#include <dlfcn.h>

#define N_NODES 500000
#define N_EDGES 32000000

// Encoded per-node contribution, padded to 16B rows for TMA gather4:
// row i = { enc_i , 0 }, enc = [cnt=1 @bit52 | cos+bias : 26b | sin+bias : 26b]
__device__ __align__(1024) ulonglong2 g_enc2[N_NODES];
// Integer accumulator (exact summation)
__device__ unsigned long long g_acc[N_NODES];

__device__ __forceinline__ void red_add_u64(unsigned long long* p, unsigned long long v) {
    asm volatile("red.global.add.u64 [%0], %1;" :: "l"(p), "l"(v) : "memory");
}
__device__ __forceinline__ unsigned smem_u32(const void* p) {
    return (unsigned)__cvta_generic_to_shared(p);
}

// Prologue: zero accumulators + encode sin/cos into padded u64 rows
__global__ void prologue_kernel(const float* __restrict__ theta) {
    int i = blockIdx.x * blockDim.x + threadIdx.x;
    if (i < N_NODES) {
        g_acc[i] = 0ULL;
        float sn, cs;
        sincosf(theta[i], &sn, &cs);
        long long si = (long long)lrintf(sn * 65536.0f) + 131072;
        long long ci = (long long)lrintf(cs * 65536.0f) + 131072;
        unsigned long long e = (1ULL << 52) | ((unsigned long long)ci << 26) | (unsigned long long)si;
        g_enc2[i] = make_ulonglong2(e, 0ULL);
    }
    cudaTriggerProgrammaticLaunchCompletion();
}

// TMA edge kernel: 1024 edges per CTA. Each thread issues one gather4 for 4 edges
// into a 128B-ALIGNED staging slot (TMA dst alignment requirement), then consumes
// 4 staged values via LDS and fires 4 u64 REDs.
__global__ void __launch_bounds__(256) edge_kernel_tma(
        const __grid_constant__ CUtensorMap tmap,
        const int4* __restrict__ src4,
        const int* __restrict__ dst) {
    // 256 slots x 128B = 32KB. Slot p holds edges 4p..4p+3 at bytes +0,+16,+32,+48.
    __shared__ __align__(1024) unsigned long long stage[4096];
    __shared__ unsigned long long mbar;
    const int tid = threadIdx.x;
    const int base = blockIdx.x * 1024;

    // Independent prefix (before PDL wait): index streaming
    int4 s = src4[(base >> 2) + tid];          // producer role: 4 src rows (edges 4*tid..4*tid+3)
    int d0 = dst[base + tid];                  // consumer role: edges base+tid+256k
    int d1 = dst[base + tid + 256];
    int d2 = dst[base + tid + 512];
    int d3 = dst[base + tid + 768];

    unsigned mb = smem_u32(&mbar);
    if (tid == 0) {
        asm volatile("mbarrier.init.shared.b64 [%0], 1;" :: "r"(mb) : "memory");
    }
    __syncthreads();

    cudaGridDependencySynchronize();           // g_enc2 ready

    if (tid == 0) {
        asm volatile("mbarrier.arrive.expect_tx.shared.b64 _, [%0], %1;"
                     :: "r"(mb), "r"(16384) : "memory");
    }
    __syncthreads();                           // expect_tx ordered before all issues

    unsigned dst_smem = smem_u32(&stage[0]) + tid * 128;   // 128B-aligned per gather
    asm volatile(
        "cp.async.bulk.tensor.2d.tile::gather4.shared::cta.global.mbarrier::complete_tx::bytes"
        " [%0], [%1, {%2, %3, %4, %5, %6}], [%7];"
        :: "r"(dst_smem), "l"(&tmap),
           "r"(0), "r"(s.x), "r"(s.y), "r"(s.z), "r"(s.w),
           "r"(mb) : "memory");

    // Wait phase 0 (acquire)
    asm volatile(
        "{\n\t.reg .pred p;\n\t"
        "WAIT%=:\n\t"
        "mbarrier.try_wait.parity.acquire.cta.shared::cta.b64 p, [%0], 0, 0x989680;\n\t"
        "@!p bra WAIT%=;\n\t}"
        :: "r"(mb) : "memory");

    // Edge e (local) lives at u64 index 16*(e>>2) + 2*(e&3)
    int e0i = tid;        // k = 0
    int e1i = tid + 256;
    int e2i = tid + 512;
    int e3i = tid + 768;
    unsigned long long v0 = stage[((e0i >> 2) << 4) + ((e0i & 3) << 1)];
    unsigned long long v1 = stage[((e1i >> 2) << 4) + ((e1i & 3) << 1)];
    unsigned long long v2 = stage[((e2i >> 2) << 4) + ((e2i & 3) << 1)];
    unsigned long long v3 = stage[((e3i >> 2) << 4) + ((e3i & 3) << 1)];

    red_add_u64(&g_acc[d0], v0);
    red_add_u64(&g_acc[d1], v1);
    red_add_u64(&g_acc[d2], v2);
    red_add_u64(&g_acc[d3], v3);

    cudaTriggerProgrammaticLaunchCompletion();
}

// Fallback edge kernel (plain LDG gather), if tensormap encode is unavailable.
__global__ void __launch_bounds__(256) edge_kernel_fallback(const int2* __restrict__ src2,
                                                            const int2* __restrict__ dst2) {
    int i = blockIdx.x * blockDim.x + threadIdx.x;
    int2 s = src2[i];
    int2 d = dst2[i];
    cudaGridDependencySynchronize();
    unsigned long long e0 = __ldg(&g_enc2[s.x].x);
    unsigned long long e1 = __ldg(&g_enc2[s.y].x);
    red_add_u64(&g_acc[d.x], e0);
    red_add_u64(&g_acc[d.y], e1);
    cudaTriggerProgrammaticLaunchCompletion();
}

// Epilogue: decode fields, w = c*(cos*Ssin - sin*Scos)/max(cnt,1); v = u0*[cos,sin]
__global__ void node_kernel(const float* __restrict__ theta,
                            const float* __restrict__ logc,
                            const float* __restrict__ u0p,
                            float* __restrict__ out) {
    int i = blockIdx.x * blockDim.x + threadIdx.x;
    if (i >= N_NODES) {
        cudaGridDependencySynchronize();
        return;
    }
    float c = expf(*logc);
    float u0 = *u0p;
    float sn, cs;
    sincosf(theta[i], &sn, &cs);

    cudaGridDependencySynchronize();

    unsigned long long a = g_acc[i];
    long long cnt    = (long long)(a >> 52);
    long long sfield = (long long)(a & 0x3FFFFFFULL);
    long long cfield = (long long)((a >> 26) & 0x3FFFFFFULL);
    float Ssin = (float)(sfield - 131072LL * cnt) * (1.0f / 65536.0f);
    float Scos = (float)(cfield - 131072LL * cnt) * (1.0f / 65536.0f);

    float denom = fmaxf((float)cnt, 1.0f);
    float w = c * (cs * Ssin - sn * Scos) / denom;

    out[3 * i + 0] = w;
    out[3 * i + 1] = u0 * cs;
    out[3 * i + 2] = u0 * sn;
}

typedef CUresult (*PFN_encodeTiled)(CUtensorMap*, CUtensorMapDataType, cuuint32_t, void*,
                                    const cuuint64_t*, const cuuint64_t*, const cuuint32_t*,
                                    const cuuint32_t*, CUtensorMapInterleave, CUtensorMapSwizzle,
                                    CUtensorMapL2promotion, CUtensorMapFloatOOBfill);

extern "C" void kernel_launch(void* const* d_in, const int* in_sizes, int n_in,
                              void* d_out, int out_size) {
    // Input order (setup_inputs): theta, logc, u0, src, dst
    const float* theta = (const float*)d_in[0];
    const float* logc  = (const float*)d_in[1];
    const float* u0    = (const float*)d_in[2];
    const int*   src   = (const int*)d_in[3];
    const int*   dst   = (const int*)d_in[4];
    float* out = (float*)d_out;

    // Build tensormap for g_enc2 as a 2D [500000 rows x 2 u64] tensor (host-side, no stream ops)
    CUtensorMap tmap;
    bool use_tma = false;
    {
        void* h = dlopen("libcuda.so.1", RTLD_NOW | RTLD_GLOBAL);
        if (h) {
            PFN_encodeTiled enc = (PFN_encodeTiled)dlsym(h, "cuTensorMapEncodeTiled");
            void* enc_addr = nullptr;
            cudaGetSymbolAddress(&enc_addr, g_enc2);
            if (enc && enc_addr) {
                cuuint64_t dims[2]    = {2, N_NODES};   // 2 u64 per row, 500k rows
                cuuint64_t strides[1] = {16};           // row stride in bytes
                cuuint32_t box[2]     = {2, 1};         // 16B per gathered row
                cuuint32_t es[2]      = {1, 1};
                if (enc(&tmap, CU_TENSOR_MAP_DATA_TYPE_UINT64, 2, enc_addr,
                        dims, strides, box, es,
                        CU_TENSOR_MAP_INTERLEAVE_NONE, CU_TENSOR_MAP_SWIZZLE_NONE,
                        CU_TENSOR_MAP_L2_PROMOTION_NONE,
                        CU_TENSOR_MAP_FLOAT_OOB_FILL_NONE) == CUDA_SUCCESS) {
                    use_tma = true;
                }
            }
        }
    }

    // Launch 1: prologue
    {
        int threads = 256;
        int blocks = (N_NODES + threads - 1) / threads;
        prologue_kernel<<<blocks, threads>>>(theta);
    }
    // Launch 2: edge kernel (PDL)
    {
        cudaLaunchConfig_t cfg = {};
        cfg.blockDim = dim3(256, 1, 1);
        cudaLaunchAttribute attr[1];
        attr[0].id = cudaLaunchAttributeProgrammaticStreamSerialization;
        attr[0].val.programmaticStreamSerializationAllowed = 1;
        cfg.attrs = attr;
        cfg.numAttrs = 1;
        if (use_tma) {
            cfg.gridDim = dim3(N_EDGES / 1024, 1, 1);  // 31250 CTAs, 1024 edges each
            cudaLaunchKernelEx(&cfg, edge_kernel_tma, tmap, (const int4*)src, dst);
        } else {
            cfg.gridDim = dim3((N_EDGES / 2) / 256, 1, 1);
            cudaLaunchKernelEx(&cfg, edge_kernel_fallback, (const int2*)src, (const int2*)dst);
        }
    }
    // Launch 3: epilogue (PDL)
    {
        cudaLaunchConfig_t cfg = {};
        cfg.blockDim = dim3(256, 1, 1);
        cfg.gridDim = dim3((N_NODES + 255) / 256, 1, 1);
        cudaLaunchAttribute attr[1];
        attr[0].id = cudaLaunchAttributeProgrammaticStreamSerialization;
        attr[0].val.programmaticStreamSerializationAllowed = 1;
        cfg.attrs = attr;
        cfg.numAttrs = 1;
        cudaLaunchKernelEx(&cfg, node_kernel, theta, logc, u0, out);
    }
}

// round 12
// speedup vs baseline: 1.0126x; 1.0126x over previous
#include <cuda_runtime.h>
#include <cuda.h>
#include <math.h>
#include <dlfcn.h>

#define N_NODES 500000
#define N_EDGES 32000000

// Encoded per-node contribution, replicated x4 into a 32B row for TMA gather4.
// enc = [cnt=1 @bit52 | cos+bias : 26b | sin+bias : 26b]
__device__ __align__(1024) ulonglong4 g_enc4[N_NODES];
// Integer accumulator (exact summation)
__device__ unsigned long long g_acc[N_NODES];

__device__ __forceinline__ void red_add_u64(unsigned long long* p, unsigned long long v) {
    asm volatile("red.global.add.u64 [%0], %1;" :: "l"(p), "l"(v) : "memory");
}
__device__ __forceinline__ unsigned smem_u32(const void* p) {
    return (unsigned)__cvta_generic_to_shared(p);
}

// Prologue: zero accumulators + encode sin/cos into replicated 32B rows
__global__ void prologue_kernel(const float* __restrict__ theta) {
    int i = blockIdx.x * blockDim.x + threadIdx.x;
    if (i < N_NODES) {
        g_acc[i] = 0ULL;
        float sn, cs;
        sincosf(theta[i], &sn, &cs);
        long long si = (long long)lrintf(sn * 65536.0f) + 131072;
        long long ci = (long long)lrintf(cs * 65536.0f) + 131072;
        unsigned long long e = (1ULL << 52) | ((unsigned long long)ci << 26) | (unsigned long long)si;
        g_enc4[i] = make_ulonglong4(e, e, e, e);
    }
    cudaTriggerProgrammaticLaunchCompletion();
}

// TMA edge kernel: 1024 edges per CTA. Thread t gathers the 4 rows for edges
// 4t..4t+3 into its fully-dense 128B slot. Consumers read back with a
// bank-spread offset (value replicated x4 per row) -> 2-way LDS conflicts only.
__global__ void __launch_bounds__(256) edge_kernel_tma(
        const __grid_constant__ CUtensorMap tmap,
        const int4* __restrict__ src4,
        const int* __restrict__ dst) {
    // 256 slots x 128B = 32KB, fully dense (4 rows x 32B per slot).
    __shared__ __align__(1024) unsigned long long stage[4096];
    __shared__ unsigned long long mbar;
    const int tid = threadIdx.x;
    const int base = blockIdx.x * 1024;

    // Independent prefix (before PDL wait): index streaming
    int4 s = src4[(base >> 2) + tid];          // src rows for edges 4*tid .. 4*tid+3
    int d0 = dst[base + tid];                  // consumer edges: tid + 256k
    int d1 = dst[base + tid + 256];
    int d2 = dst[base + tid + 512];
    int d3 = dst[base + tid + 768];

    unsigned mb = smem_u32(&mbar);
    if (tid == 0) {
        asm volatile("mbarrier.init.shared.b64 [%0], 1;" :: "r"(mb) : "memory");
    }
    __syncthreads();

    cudaGridDependencySynchronize();           // g_enc4 ready

    if (tid == 0) {
        asm volatile("mbarrier.arrive.expect_tx.shared.b64 _, [%0], %1;"
                     :: "r"(mb), "r"(32768) : "memory");
    }
    __syncthreads();                           // expect_tx ordered before all issues

    unsigned dst_smem = smem_u32(&stage[0]) + tid * 128;   // 128B-aligned slot
    asm volatile(
        "cp.async.bulk.tensor.2d.tile::gather4.shared::cta.global.mbarrier::complete_tx::bytes"
        " [%0], [%1, {%2, %3, %4, %5, %6}], [%7];"
        :: "r"(dst_smem), "l"(&tmap),
           "r"(0), "r"(s.x), "r"(s.y), "r"(s.z), "r"(s.w),
           "r"(mb) : "memory");

    // Wait phase 0 (acquire)
    asm volatile(
        "{\n\t.reg .pred p;\n\t"
        "WAIT%=:\n\t"
        "mbarrier.try_wait.parity.acquire.cta.shared::cta.b64 p, [%0], 0, 0x989680;\n\t"
        "@!p bra WAIT%=;\n\t}"
        :: "r"(mb) : "memory");

    // Edge e lives in slot e>>2, row e&3 (4 replicated u64s at u64 idx 16*(e>>2)+4*(e&3)+m).
    // Pick m=(tid>>2)&3 so a warp's 32 lanes cover all 16 even bank-pairs -> 2-way conflicts.
    const int m = (tid >> 2) & 3;
    int e0 = tid;
    int e1 = tid + 256;
    int e2 = tid + 512;
    int e3 = tid + 768;
    unsigned long long v0 = stage[((e0 >> 2) << 4) + ((e0 & 3) << 2) + m];
    unsigned long long v1 = stage[((e1 >> 2) << 4) + ((e1 & 3) << 2) + m];
    unsigned long long v2 = stage[((e2 >> 2) << 4) + ((e2 & 3) << 2) + m];
    unsigned long long v3 = stage[((e3 >> 2) << 4) + ((e3 & 3) << 2) + m];

    red_add_u64(&g_acc[d0], v0);
    red_add_u64(&g_acc[d1], v1);
    red_add_u64(&g_acc[d2], v2);
    red_add_u64(&g_acc[d3], v3);

    cudaTriggerProgrammaticLaunchCompletion();
}

// Fallback edge kernel (plain LDG gather), if tensormap encode is unavailable.
__global__ void __launch_bounds__(256) edge_kernel_fallback(const int2* __restrict__ src2,
                                                            const int2* __restrict__ dst2) {
    int i = blockIdx.x * blockDim.x + threadIdx.x;
    int2 s = src2[i];
    int2 d = dst2[i];
    cudaGridDependencySynchronize();
    unsigned long long e0 = __ldg(&g_enc4[s.x].x);
    unsigned long long e1 = __ldg(&g_enc4[s.y].x);
    red_add_u64(&g_acc[d.x], e0);
    red_add_u64(&g_acc[d.y], e1);
    cudaTriggerProgrammaticLaunchCompletion();
}

// Epilogue: decode fields, w = c*(cos*Ssin - sin*Scos)/max(cnt,1); v = u0*[cos,sin]
__global__ void node_kernel(const float* __restrict__ theta,
                            const float* __restrict__ logc,
                            const float* __restrict__ u0p,
                            float* __restrict__ out) {
    int i = blockIdx.x * blockDim.x + threadIdx.x;
    if (i >= N_NODES) {
        cudaGridDependencySynchronize();
        return;
    }
    float c = expf(*logc);
    float u0 = *u0p;
    float sn, cs;
    sincosf(theta[i], &sn, &cs);

    cudaGridDependencySynchronize();

    unsigned long long a = g_acc[i];
    long long cnt    = (long long)(a >> 52);
    long long sfield = (long long)(a & 0x3FFFFFFULL);
    long long cfield = (long long)((a >> 26) & 0x3FFFFFFULL);
    float Ssin = (float)(sfield - 131072LL * cnt) * (1.0f / 65536.0f);
    float Scos = (float)(cfield - 131072LL * cnt) * (1.0f / 65536.0f);

    float denom = fmaxf((float)cnt, 1.0f);
    float w = c * (cs * Ssin - sn * Scos) / denom;

    out[3 * i + 0] = w;
    out[3 * i + 1] = u0 * cs;
    out[3 * i + 2] = u0 * sn;
}

typedef CUresult (*PFN_encodeTiled)(CUtensorMap*, CUtensorMapDataType, cuuint32_t, void*,
                                    const cuuint64_t*, const cuuint64_t*, const cuuint32_t*,
                                    const cuuint32_t*, CUtensorMapInterleave, CUtensorMapSwizzle,
                                    CUtensorMapL2promotion, CUtensorMapFloatOOBfill);

extern "C" void kernel_launch(void* const* d_in, const int* in_sizes, int n_in,
                              void* d_out, int out_size) {
    // Input order (setup_inputs): theta, logc, u0, src, dst
    const float* theta = (const float*)d_in[0];
    const float* logc  = (const float*)d_in[1];
    const float* u0    = (const float*)d_in[2];
    const int*   src   = (const int*)d_in[3];
    const int*   dst   = (const int*)d_in[4];
    float* out = (float*)d_out;

    // Tensormap for g_enc4 as 2D [500000 rows x 4 u64] (host-side, no stream ops)
    CUtensorMap tmap;
    bool use_tma = false;
    {
        void* h = dlopen("libcuda.so.1", RTLD_NOW | RTLD_GLOBAL);
        if (h) {
            PFN_encodeTiled enc = (PFN_encodeTiled)dlsym(h, "cuTensorMapEncodeTiled");
            void* enc_addr = nullptr;
            cudaGetSymbolAddress(&enc_addr, g_enc4);
            if (enc && enc_addr) {
                cuuint64_t dims[2]    = {4, N_NODES};   // 4 u64 per row, 500k rows
                cuuint64_t strides[1] = {32};           // row stride in bytes
                cuuint32_t box[2]     = {4, 1};         // 32B per gathered row
                cuuint32_t es[2]      = {1, 1};
                if (enc(&tmap, CU_TENSOR_MAP_DATA_TYPE_UINT64, 2, enc_addr,
                        dims, strides, box, es,
                        CU_TENSOR_MAP_INTERLEAVE_NONE, CU_TENSOR_MAP_SWIZZLE_NONE,
                        CU_TENSOR_MAP_L2_PROMOTION_NONE,
                        CU_TENSOR_MAP_FLOAT_OOB_FILL_NONE) == CUDA_SUCCESS) {
                    use_tma = true;
                }
            }
        }
    }

    // Launch 1: prologue
    {
        int threads = 256;
        int blocks = (N_NODES + threads - 1) / threads;
        prologue_kernel<<<blocks, threads>>>(theta);
    }
    // Launch 2: edge kernel (PDL)
    {
        cudaLaunchConfig_t cfg = {};
        cfg.blockDim = dim3(256, 1, 1);
        cudaLaunchAttribute attr[1];
        attr[0].id = cudaLaunchAttributeProgrammaticStreamSerialization;
        attr[0].val.programmaticStreamSerializationAllowed = 1;
        cfg.attrs = attr;
        cfg.numAttrs = 1;
        if (use_tma) {
            cfg.gridDim = dim3(N_EDGES / 1024, 1, 1);  // 31250 CTAs, 1024 edges each
            cudaLaunchKernelEx(&cfg, edge_kernel_tma, tmap, (const int4*)src, dst);
        } else {
            cfg.gridDim = dim3((N_EDGES / 2) / 256, 1, 1);
            cudaLaunchKernelEx(&cfg, edge_kernel_fallback, (const int2*)src, (const int2*)dst);
        }
    }
    // Launch 3: epilogue (PDL)
    {
        cudaLaunchConfig_t cfg = {};
        cfg.blockDim = dim3(256, 1, 1);
        cfg.gridDim = dim3((N_NODES + 255) / 256, 1, 1);
        cudaLaunchAttribute attr[1];
        attr[0].id = cudaLaunchAttributeProgrammaticStreamSerialization;
        attr[0].val.programmaticStreamSerializationAllowed = 1;
        cfg.attrs = attr;
        cfg.numAttrs = 1;
        cudaLaunchKernelEx(&cfg, node_kernel, theta, logc, u0, out);
    }
}

// round 13
// speedup vs baseline: 1.0300x; 1.0172x over previous
#include <cuda_runtime.h>
#include <math.h>

#define N_NODES 500000
#define N_EDGES 32000000

// Per-node pre-encoded contribution: [cnt=1 @bit52 | cos+bias : 26b | sin+bias : 26b]
// field = round(65536*x) + 131072, in [65536, 196608] (non-negative).
__device__ unsigned long long g_enc[N_NODES];
// Integer accumulator (exact summation)
__device__ unsigned long long g_acc[N_NODES];

__device__ __forceinline__ void red_add_u64(unsigned long long* p, unsigned long long v) {
    asm volatile("red.global.add.u64 [%0], %1;" :: "l"(p), "l"(v) : "memory");
}

// Prologue: zero accumulators + encode sin/cos of theta into u64
__global__ void prologue_kernel(const float* __restrict__ theta) {
    int i = blockIdx.x * blockDim.x + threadIdx.x;
    if (i < N_NODES) {
        g_acc[i] = 0ULL;
        float t = theta[i];
        float sn = __sinf(t);
        float cs = __cosf(t);
        long long si = (long long)lrintf(sn * 65536.0f) + 131072;
        long long ci = (long long)lrintf(cs * 65536.0f) + 131072;
        g_enc[i] = (1ULL << 52) | ((unsigned long long)ci << 26) | (unsigned long long)si;
    }
    cudaTriggerProgrammaticLaunchCompletion();
}

// Edge kernel: 4 edges/thread via int4 index loads. Per edge: one 8B random
// gather + one u64 RED. Bound by LTS op rate (~3 slots/edge) — structural wall.
__global__ void __launch_bounds__(256) edge_kernel(const int4* __restrict__ src4,
                                                   const int4* __restrict__ dst4) {
    int i = blockIdx.x * blockDim.x + threadIdx.x;

    // Independent prefix (before PDL wait): stream indices
    int4 s = src4[i];
    int4 d = dst4[i];

    cudaGridDependencySynchronize();  // g_enc / g_acc ready

    unsigned long long e0 = __ldg(&g_enc[s.x]);
    unsigned long long e1 = __ldg(&g_enc[s.y]);
    red_add_u64(&g_acc[d.x], e0);
    unsigned long long e2 = __ldg(&g_enc[s.z]);
    red_add_u64(&g_acc[d.y], e1);
    unsigned long long e3 = __ldg(&g_enc[s.w]);
    red_add_u64(&g_acc[d.z], e2);
    red_add_u64(&g_acc[d.w], e3);

    cudaTriggerProgrammaticLaunchCompletion();
}

// Epilogue: decode fields, w = c*(cos*Ssin - sin*Scos)/max(cnt,1); v = u0*[cos,sin]
__global__ void node_kernel(const float* __restrict__ theta,
                            const float* __restrict__ logc,
                            const float* __restrict__ u0p,
                            float* __restrict__ out) {
    int i = blockIdx.x * blockDim.x + threadIdx.x;
    if (i >= N_NODES) {
        cudaGridDependencySynchronize();
        return;
    }
    // Independent prefix
    float c = __expf(*logc);
    float u0 = *u0p;
    float t = theta[i];
    float sn = __sinf(t);
    float cs = __cosf(t);

    cudaGridDependencySynchronize();  // edge atomics complete

    unsigned long long a = g_acc[i];
    long long cnt    = (long long)(a >> 52);
    long long sfield = (long long)(a & 0x3FFFFFFULL);
    long long cfield = (long long)((a >> 26) & 0x3FFFFFFULL);
    float Ssin = (float)(sfield - 131072LL * cnt) * (1.0f / 65536.0f);
    float Scos = (float)(cfield - 131072LL * cnt) * (1.0f / 65536.0f);

    float denom = fmaxf((float)cnt, 1.0f);
    float w = c * (cs * Ssin - sn * Scos) / denom;

    out[3 * i + 0] = w;
    out[3 * i + 1] = u0 * cs;
    out[3 * i + 2] = u0 * sn;
}

extern "C" void kernel_launch(void* const* d_in, const int* in_sizes, int n_in,
                              void* d_out, int out_size) {
    // Input order (setup_inputs): theta, logc, u0, src, dst
    const float* theta = (const float*)d_in[0];
    const float* logc  = (const float*)d_in[1];
    const float* u0    = (const float*)d_in[2];
    const int*   src   = (const int*)d_in[3];
    const int*   dst   = (const int*)d_in[4];
    float* out = (float*)d_out;

    const int nquads = N_EDGES / 4;  // 8M, exactly 31250 blocks of 256

    // Launch 1: prologue
    {
        int threads = 256;
        int blocks = (N_NODES + threads - 1) / threads;
        prologue_kernel<<<blocks, threads>>>(theta);
    }
    // Launch 2: edge kernel (PDL)
    {
        cudaLaunchConfig_t cfg = {};
        cfg.blockDim = dim3(256, 1, 1);
        cfg.gridDim = dim3(nquads / 256, 1, 1);
        cudaLaunchAttribute attr[1];
        attr[0].id = cudaLaunchAttributeProgrammaticStreamSerialization;
        attr[0].val.programmaticStreamSerializationAllowed = 1;
        cfg.attrs = attr;
        cfg.numAttrs = 1;
        cudaLaunchKernelEx(&cfg, edge_kernel, (const int4*)src, (const int4*)dst);
    }
    // Launch 3: epilogue (PDL)
    {
        cudaLaunchConfig_t cfg = {};
        cfg.blockDim = dim3(256, 1, 1);
        cfg.gridDim = dim3((N_NODES + 255) / 256, 1, 1);
        cudaLaunchAttribute attr[1];
        attr[0].id = cudaLaunchAttributeProgrammaticStreamSerialization;
        attr[0].val.programmaticStreamSerializationAllowed = 1;
        cfg.attrs = attr;
        cfg.numAttrs = 1;
        cudaLaunchKernelEx(&cfg, node_kernel, theta, logc, u0, out);
    }
}

// round 14
// speedup vs baseline: 1.0344x; 1.0043x over previous
#include <cuda_runtime.h>
#include <math.h>

#define N_NODES 500000
#define N_EDGES 32000000

// Per-node packed contribution: u32 = [cos16 | sin16], x16 = round(16384*x)+16384.
__device__ unsigned int g_enc[N_NODES];
// Integer accumulator: [cnt @bit52 | sum cos16 : 26b | sum sin16 : 26b] (exact)
__device__ unsigned long long g_acc[N_NODES];

__device__ __forceinline__ void red_add_u64(unsigned long long* p, unsigned long long v) {
    asm volatile("red.global.add.u64 [%0], %1;" :: "l"(p), "l"(v) : "memory");
}

// Prologue: zero accumulators + pack sin/cos of theta into u32
__global__ void prologue_kernel(const float* __restrict__ theta) {
    int i = blockIdx.x * blockDim.x + threadIdx.x;
    if (i < N_NODES) {
        g_acc[i] = 0ULL;
        float t = theta[i];
        unsigned int si = (unsigned int)(lrintf(__sinf(t) * 16384.0f) + 16384);
        unsigned int ci = (unsigned int)(lrintf(__cosf(t) * 16384.0f) + 16384);
        g_enc[i] = (ci << 16) | si;
    }
    cudaTriggerProgrammaticLaunchCompletion();
}

// Expand packed u32 to the u64 RED operand: cnt=1 @52, cos field @26, sin field @0.
__device__ __forceinline__ unsigned long long expand(unsigned int e) {
    return (1ULL << 52) | ((unsigned long long)(e >> 16) << 26)
                        | (unsigned long long)(e & 0xFFFFu);
}

// Edge kernel: 4 edges/thread. Per edge: one 4B random gather (2MB table,
// better L1 hit rate) + 3 ALU expand + one u64 RED. LTS-op bound.
__global__ void __launch_bounds__(256) edge_kernel(const int4* __restrict__ src4,
                                                   const int4* __restrict__ dst4) {
    int i = blockIdx.x * blockDim.x + threadIdx.x;

    // Independent prefix (before PDL wait): stream indices
    int4 s = src4[i];
    int4 d = dst4[i];

    cudaGridDependencySynchronize();  // g_enc / g_acc ready

    unsigned int e0 = __ldg(&g_enc[s.x]);
    unsigned int e1 = __ldg(&g_enc[s.y]);
    red_add_u64(&g_acc[d.x], expand(e0));
    unsigned int e2 = __ldg(&g_enc[s.z]);
    red_add_u64(&g_acc[d.y], expand(e1));
    unsigned int e3 = __ldg(&g_enc[s.w]);
    red_add_u64(&g_acc[d.z], expand(e2));
    red_add_u64(&g_acc[d.w], expand(e3));

    cudaTriggerProgrammaticLaunchCompletion();
}

// Epilogue: decode fields, w = c*(cos*Ssin - sin*Scos)/max(cnt,1); v = u0*[cos,sin]
__global__ void node_kernel(const float* __restrict__ theta,
                            const float* __restrict__ logc,
                            const float* __restrict__ u0p,
                            float* __restrict__ out) {
    int i = blockIdx.x * blockDim.x + threadIdx.x;
    if (i >= N_NODES) {
        cudaGridDependencySynchronize();
        return;
    }
    // Independent prefix
    float c = __expf(*logc);
    float u0 = *u0p;
    float t = theta[i];
    float sn = __sinf(t);
    float cs = __cosf(t);

    cudaGridDependencySynchronize();  // edge atomics complete

    unsigned long long a = g_acc[i];
    long long cnt    = (long long)(a >> 52);
    long long sfield = (long long)(a & 0x3FFFFFFULL);
    long long cfield = (long long)((a >> 26) & 0x3FFFFFFULL);
    // exact integer de-bias (bias 16384 per contribution), then scale by 1/16384
    float Ssin = (float)(sfield - 16384LL * cnt) * (1.0f / 16384.0f);
    float Scos = (float)(cfield - 16384LL * cnt) * (1.0f / 16384.0f);

    float denom = fmaxf((float)cnt, 1.0f);
    float w = c * (cs * Ssin - sn * Scos) / denom;

    out[3 * i + 0] = w;
    out[3 * i + 1] = u0 * cs;
    out[3 * i + 2] = u0 * sn;
}

extern "C" void kernel_launch(void* const* d_in, const int* in_sizes, int n_in,
                              void* d_out, int out_size) {
    // Input order (setup_inputs): theta, logc, u0, src, dst
    const float* theta = (const float*)d_in[0];
    const float* logc  = (const float*)d_in[1];
    const float* u0    = (const float*)d_in[2];
    const int*   src   = (const int*)d_in[3];
    const int*   dst   = (const int*)d_in[4];
    float* out = (float*)d_out;

    const int nquads = N_EDGES / 4;  // 8M, exactly 31250 blocks of 256

    // Launch 1: prologue
    {
        int threads = 256;
        int blocks = (N_NODES + threads - 1) / threads;
        prologue_kernel<<<blocks, threads>>>(theta);
    }
    // Launch 2: edge kernel (PDL)
    {
        cudaLaunchConfig_t cfg = {};
        cfg.blockDim = dim3(256, 1, 1);
        cfg.gridDim = dim3(nquads / 256, 1, 1);
        cudaLaunchAttribute attr[1];
        attr[0].id = cudaLaunchAttributeProgrammaticStreamSerialization;
        attr[0].val.programmaticStreamSerializationAllowed = 1;
        cfg.attrs = attr;
        cfg.numAttrs = 1;
        cudaLaunchKernelEx(&cfg, edge_kernel, (const int4*)src, (const int4*)dst);
    }
    // Launch 3: epilogue (PDL)
    {
        cudaLaunchConfig_t cfg = {};
        cfg.blockDim = dim3(256, 1, 1);
        cfg.gridDim = dim3((N_NODES + 255) / 256, 1, 1);
        cudaLaunchAttribute attr[1];
        attr[0].id = cudaLaunchAttributeProgrammaticStreamSerialization;
        attr[0].val.programmaticStreamSerializationAllowed = 1;
        cfg.attrs = attr;
        cfg.numAttrs = 1;
        cudaLaunchKernelEx(&cfg, node_kernel, theta, logc, u0, out);
    }
}

// round 15
// speedup vs baseline: 1.0370x; 1.0025x over previous
#include <cuda_runtime.h>
#include <math.h>

#define N_NODES 500000
#define N_EDGES 32000000

// Per-node packed contribution: u32 = [cos16 | sin16], x16 = round(16384*x)+16384.
__device__ unsigned int g_enc[N_NODES];
// Integer accumulator: [cnt @bit52 | sum cos16 : 26b | sum sin16 : 26b] (exact)
__device__ unsigned long long g_acc[N_NODES];

__device__ __forceinline__ void red_add_u64(unsigned long long* p, unsigned long long v) {
    asm volatile("red.global.add.u64 [%0], %1;" :: "l"(p), "l"(v) : "memory");
}

// Prologue: zero accumulators + pack sin/cos of theta into u32
__global__ void prologue_kernel(const float* __restrict__ theta) {
    int i = blockIdx.x * blockDim.x + threadIdx.x;
    if (i < N_NODES) {
        g_acc[i] = 0ULL;
        float t = theta[i];
        unsigned int si = (unsigned int)(lrintf(__sinf(t) * 16384.0f) + 16384);
        unsigned int ci = (unsigned int)(lrintf(__cosf(t) * 16384.0f) + 16384);
        g_enc[i] = (ci << 16) | si;
    }
    cudaTriggerProgrammaticLaunchCompletion();
}

// Expand packed u32 to the u64 RED operand: cnt=1 @52, cos field @26, sin field @0.
__device__ __forceinline__ unsigned long long expand(unsigned int e) {
    return (1ULL << 52) | ((unsigned long long)(e >> 16) << 26)
                        | (unsigned long long)(e & 0xFFFFu);
}

// Edge kernel: 4 edges/thread, 512-thread CTAs (half the CTA count -> less
// scheduling overhead). Per edge: one 4B random gather + one u64 RED.
// Bound by LTS atomic-RMW + gather slot rate — structural wall (~239us).
__global__ void __launch_bounds__(512) edge_kernel(const int4* __restrict__ src4,
                                                   const int4* __restrict__ dst4) {
    int i = blockIdx.x * blockDim.x + threadIdx.x;

    // Independent prefix (before PDL wait): stream indices
    int4 s = src4[i];
    int4 d = dst4[i];

    cudaGridDependencySynchronize();  // g_enc / g_acc ready

    unsigned int e0 = __ldg(&g_enc[s.x]);
    unsigned int e1 = __ldg(&g_enc[s.y]);
    red_add_u64(&g_acc[d.x], expand(e0));
    unsigned int e2 = __ldg(&g_enc[s.z]);
    red_add_u64(&g_acc[d.y], expand(e1));
    unsigned int e3 = __ldg(&g_enc[s.w]);
    red_add_u64(&g_acc[d.z], expand(e2));
    red_add_u64(&g_acc[d.w], expand(e3));

    cudaTriggerProgrammaticLaunchCompletion();
}

// Epilogue: decode fields, w = c*(cos*Ssin - sin*Scos)/max(cnt,1); v = u0*[cos,sin]
__global__ void __launch_bounds__(512) node_kernel(const float* __restrict__ theta,
                            const float* __restrict__ logc,
                            const float* __restrict__ u0p,
                            float* __restrict__ out) {
    int i = blockIdx.x * blockDim.x + threadIdx.x;
    if (i >= N_NODES) {
        cudaGridDependencySynchronize();
        return;
    }
    // Independent prefix
    float c = __expf(*logc);
    float u0 = *u0p;
    float t = theta[i];
    float sn = __sinf(t);
    float cs = __cosf(t);

    cudaGridDependencySynchronize();  // edge atomics complete

    unsigned long long a = g_acc[i];
    long long cnt    = (long long)(a >> 52);
    long long sfield = (long long)(a & 0x3FFFFFFULL);
    long long cfield = (long long)((a >> 26) & 0x3FFFFFFULL);
    // exact integer de-bias (bias 16384 per contribution), then scale by 1/16384
    float Ssin = (float)(sfield - 16384LL * cnt) * (1.0f / 16384.0f);
    float Scos = (float)(cfield - 16384LL * cnt) * (1.0f / 16384.0f);

    float denom = fmaxf((float)cnt, 1.0f);
    float w = c * (cs * Ssin - sn * Scos) / denom;

    out[3 * i + 0] = w;
    out[3 * i + 1] = u0 * cs;
    out[3 * i + 2] = u0 * sn;
}

extern "C" void kernel_launch(void* const* d_in, const int* in_sizes, int n_in,
                              void* d_out, int out_size) {
    // Input order (setup_inputs): theta, logc, u0, src, dst
    const float* theta = (const float*)d_in[0];
    const float* logc  = (const float*)d_in[1];
    const float* u0    = (const float*)d_in[2];
    const int*   src   = (const int*)d_in[3];
    const int*   dst   = (const int*)d_in[4];
    float* out = (float*)d_out;

    const int nquads = N_EDGES / 4;  // 8M, exactly 15625 blocks of 512

    // Launch 1: prologue
    {
        int threads = 256;
        int blocks = (N_NODES + threads - 1) / threads;
        prologue_kernel<<<blocks, threads>>>(theta);
    }
    // Launch 2: edge kernel (PDL)
    {
        cudaLaunchConfig_t cfg = {};
        cfg.blockDim = dim3(512, 1, 1);
        cfg.gridDim = dim3(nquads / 512, 1, 1);
        cudaLaunchAttribute attr[1];
        attr[0].id = cudaLaunchAttributeProgrammaticStreamSerialization;
        attr[0].val.programmaticStreamSerializationAllowed = 1;
        cfg.attrs = attr;
        cfg.numAttrs = 1;
        cudaLaunchKernelEx(&cfg, edge_kernel, (const int4*)src, (const int4*)dst);
    }
    // Launch 3: epilogue (PDL)
    {
        cudaLaunchConfig_t cfg = {};
        cfg.blockDim = dim3(512, 1, 1);
        cfg.gridDim = dim3((N_NODES + 511) / 512, 1, 1);
        cudaLaunchAttribute attr[1];
        attr[0].id = cudaLaunchAttributeProgrammaticStreamSerialization;
        attr[0].val.programmaticStreamSerializationAllowed = 1;
        cfg.attrs = attr;
        cfg.numAttrs = 1;
        cudaLaunchKernelEx(&cfg, node_kernel, theta, logc, u0, out);
    }
}